// round 1
// baseline (speedup 1.0000x reference)
#include <cuda_runtime.h>
#include <math.h>
#include <stdint.h>
#include <stddef.h>

#define B_Q 1024
#define N_C 16384
#define D_M 1024
#define NH  8
#define HDIM 128

// ---------------- static scratch (no allocs allowed) ----------------
__device__ float g_bufA[(size_t)N_C * D_M];   // 64 MB: Tk -> kp
__device__ float g_bufB[(size_t)N_C * D_M];   // 64 MB: Hk -> kh
__device__ float g_S[(size_t)B_Q * N_C];      // 64 MB: qp @ kp^T
__device__ float g_scores[(size_t)NH * B_Q * N_C]; // 512 MB: [H][B][N]
__device__ float g_Tq[B_Q * D_M];
__device__ float g_Hq[B_Q * D_M];
__device__ float g_qp[B_Q * D_M];
__device__ float g_qh[B_Q * D_M];
__device__ float g_qsq[B_Q], g_qinv[B_Q];
__device__ float g_ksq[N_C], g_kinv[N_C];
__device__ float g_m[NH * B_Q], g_l[NH * B_Q];

// ---------------- reductions ----------------
__device__ __forceinline__ float blockReduceSum(float v) {
    __shared__ float sh[32];
    int lane = threadIdx.x & 31, w = threadIdx.x >> 5;
    #pragma unroll
    for (int o = 16; o > 0; o >>= 1) v += __shfl_down_sync(0xffffffffu, v, o);
    __syncthreads();
    if (lane == 0) sh[w] = v;
    __syncthreads();
    float r = 0.f;
    if (threadIdx.x < (blockDim.x >> 5)) r = sh[threadIdx.x];
    if (w == 0) {
        #pragma unroll
        for (int o = 4; o > 0; o >>= 1) r += __shfl_down_sync(0xffffffffu, r, o);
    }
    if (threadIdx.x == 0) sh[0] = r;
    __syncthreads();
    return sh[0];
}

__device__ __forceinline__ float blockReduceMax(float v) {
    __shared__ float sh[32];
    int lane = threadIdx.x & 31, w = threadIdx.x >> 5;
    #pragma unroll
    for (int o = 16; o > 0; o >>= 1) v = fmaxf(v, __shfl_down_sync(0xffffffffu, v, o));
    __syncthreads();
    if (lane == 0) sh[w] = v;
    __syncthreads();
    float r = -INFINITY;
    if (threadIdx.x < (blockDim.x >> 5)) r = sh[threadIdx.x];
    if (w == 0) {
        #pragma unroll
        for (int o = 4; o > 0; o >>= 1) r = fmaxf(r, __shfl_down_sync(0xffffffffu, r, o));
    }
    if (threadIdx.x == 0) sh[0] = r;
    __syncthreads();
    return sh[0];
}

// ---------------- GEMM NN: C[M,N] = A[M,K] @ B[K,N] + bias ----------------
// Tiles: 128x128x8, 256 threads, 8x8 per thread. All dims divisible.
template <bool BIAS>
__global__ __launch_bounds__(256)
void gemm_nn(const float* __restrict__ A, const float* __restrict__ Bm,
             const float* __restrict__ bias, float* __restrict__ C,
             int M, int N, int K)
{
    __shared__ float As[8][128];
    __shared__ float Bs[8][128];
    const int t = threadIdx.x;
    const int tx = t & 15, ty = t >> 4;
    const int m0 = blockIdx.y * 128, n0 = blockIdx.x * 128;
    const int lr = t >> 1;          // 0..127
    const int lc = (t & 1) * 4;     // 0 or 4
    const int bk = t >> 5;          // 0..7
    const int bn = (t & 31) * 4;    // 0..124

    float acc[8][8];
    #pragma unroll
    for (int i = 0; i < 8; i++)
        #pragma unroll
        for (int j = 0; j < 8; j++) acc[i][j] = 0.f;

    for (int k0 = 0; k0 < K; k0 += 8) {
        float4 av = *(const float4*)(A + (size_t)(m0 + lr) * K + k0 + lc);
        As[lc + 0][lr] = av.x; As[lc + 1][lr] = av.y;
        As[lc + 2][lr] = av.z; As[lc + 3][lr] = av.w;
        float4 bv = *(const float4*)(Bm + (size_t)(k0 + bk) * N + n0 + bn);
        *(float4*)&Bs[bk][bn] = bv;
        __syncthreads();
        #pragma unroll
        for (int kk = 0; kk < 8; kk++) {
            float a[8], b[8];
            *(float4*)(a)     = *(const float4*)&As[kk][ty * 8];
            *(float4*)(a + 4) = *(const float4*)&As[kk][ty * 8 + 4];
            *(float4*)(b)     = *(const float4*)&Bs[kk][tx * 8];
            *(float4*)(b + 4) = *(const float4*)&Bs[kk][tx * 8 + 4];
            #pragma unroll
            for (int i = 0; i < 8; i++)
                #pragma unroll
                for (int j = 0; j < 8; j++)
                    acc[i][j] = fmaf(a[i], b[j], acc[i][j]);
        }
        __syncthreads();
    }

    #pragma unroll
    for (int i = 0; i < 8; i++) {
        size_t row = (size_t)(m0 + ty * 8 + i) * N + n0 + tx * 8;
        #pragma unroll
        for (int j = 0; j < 8; j++) {
            float v = acc[i][j];
            if (BIAS) v += bias[n0 + tx * 8 + j];
            C[row + j] = v;
        }
    }
}

// ---------------- GEMM NT: C[M,N] = alpha * A[M,K] @ B[N,K]^T ----------------
// blockIdx.z selects a head: A += z*a_off (column offset within lda rows),
// B += z*b_off, C += z*c_stride.
__global__ __launch_bounds__(256)
void gemm_nt(const float* __restrict__ A, const float* __restrict__ Bm,
             float* __restrict__ C, int M, int N, int K,
             int lda, int ldb, float alpha,
             int a_off, int b_off, size_t c_stride)
{
    __shared__ float As[8][128];
    __shared__ float Bs[8][128];
    const float* Ah = A + (size_t)blockIdx.z * a_off;
    const float* Bh = Bm + (size_t)blockIdx.z * b_off;
    float* Ch = C + (size_t)blockIdx.z * c_stride;

    const int t = threadIdx.x;
    const int tx = t & 15, ty = t >> 4;
    const int m0 = blockIdx.y * 128, n0 = blockIdx.x * 128;
    const int lr = t >> 1;
    const int lc = (t & 1) * 4;

    float acc[8][8];
    #pragma unroll
    for (int i = 0; i < 8; i++)
        #pragma unroll
        for (int j = 0; j < 8; j++) acc[i][j] = 0.f;

    for (int k0 = 0; k0 < K; k0 += 8) {
        float4 av = *(const float4*)(Ah + (size_t)(m0 + lr) * lda + k0 + lc);
        As[lc + 0][lr] = av.x; As[lc + 1][lr] = av.y;
        As[lc + 2][lr] = av.z; As[lc + 3][lr] = av.w;
        float4 bv = *(const float4*)(Bh + (size_t)(n0 + lr) * ldb + k0 + lc);
        Bs[lc + 0][lr] = bv.x; Bs[lc + 1][lr] = bv.y;
        Bs[lc + 2][lr] = bv.z; Bs[lc + 3][lr] = bv.w;
        __syncthreads();
        #pragma unroll
        for (int kk = 0; kk < 8; kk++) {
            float a[8], b[8];
            *(float4*)(a)     = *(const float4*)&As[kk][ty * 8];
            *(float4*)(a + 4) = *(const float4*)&As[kk][ty * 8 + 4];
            *(float4*)(b)     = *(const float4*)&Bs[kk][tx * 8];
            *(float4*)(b + 4) = *(const float4*)&Bs[kk][tx * 8 + 4];
            #pragma unroll
            for (int i = 0; i < 8; i++)
                #pragma unroll
                for (int j = 0; j < 8; j++)
                    acc[i][j] = fmaf(a[i], b[j], acc[i][j]);
        }
        __syncthreads();
    }

    #pragma unroll
    for (int i = 0; i < 8; i++) {
        size_t row = (size_t)(m0 + ty * 8 + i) * N + n0 + tx * 8;
        #pragma unroll
        for (int j = 0; j < 8; j++)
            Ch[row + j] = alpha * acc[i][j];
    }
}

// ---------------- LayerNorm + exact GELU (row = D_M) ----------------
__global__ void ln_gelu(const float* __restrict__ X, const float* __restrict__ g,
                        const float* __restrict__ be, float* __restrict__ Y)
{
    const int row = blockIdx.x;
    const float* x = X + (size_t)row * D_M;
    float xv[4];
    #pragma unroll
    for (int i = 0; i < 4; i++) xv[i] = x[threadIdx.x + i * 256];
    float s = xv[0] + xv[1] + xv[2] + xv[3];
    float mu = blockReduceSum(s) * (1.f / D_M);
    float v = 0.f;
    #pragma unroll
    for (int i = 0; i < 4; i++) { float d = xv[i] - mu; v += d * d; }
    float var = blockReduceSum(v) * (1.f / D_M);
    float rstd = rsqrtf(var + 1e-5f);
    #pragma unroll
    for (int i = 0; i < 4; i++) {
        int c = threadIdx.x + i * 256;
        float y = (xv[i] - mu) * rstd * g[c] + be[c];
        Y[(size_t)row * D_M + c] = y * 0.5f * (1.f + erff(y * 0.70710678118654752f));
    }
}

// ---------------- per-row sumsq + 1/norm ----------------
__global__ void row_stats(const float* __restrict__ X, float* __restrict__ sq,
                          float* __restrict__ inv)
{
    const int row = blockIdx.x;
    const float* x = X + (size_t)row * D_M;
    float s = 0.f;
    for (int i = threadIdx.x; i < D_M; i += 256) { float v = x[i]; s = fmaf(v, v, s); }
    float tot = blockReduceSum(s);
    if (threadIdx.x == 0) { sq[row] = tot; inv[row] = rsqrtf(tot); }
}

// ---------------- softmax stats over N per (h,b) row ----------------
__global__ void softmax_stats(const float* __restrict__ Sc, float* __restrict__ m,
                              float* __restrict__ l)
{
    const int r = blockIdx.x;  // h*B_Q + b
    const float* x = Sc + (size_t)r * N_C;
    float mx = -INFINITY;
    for (int i = threadIdx.x; i < N_C; i += 256) mx = fmaxf(mx, x[i]);
    mx = blockReduceMax(mx);
    float s = 0.f;
    for (int i = threadIdx.x; i < N_C; i += 256) s += expf(x[i] - mx);
    float tot = blockReduceSum(s);
    if (threadIdx.x == 0) { m[r] = mx; l[r] = tot; }
}

// ---------------- fused features + MLP epilogue ----------------
__global__ __launch_bounds__(256)
void fuse(const float* __restrict__ S, const float* __restrict__ scores,
          const float* __restrict__ qsq, const float* __restrict__ qinv,
          const float* __restrict__ ksq, const float* __restrict__ kinv,
          const float* __restrict__ m, const float* __restrict__ l,
          const float* __restrict__ temp,
          const float* __restrict__ fw1, const float* __restrict__ fb1,
          const float* __restrict__ fw2, const float* __restrict__ fb2,
          float* __restrict__ out)
{
    __shared__ float w1s[192], b1s[64], w2s[64];
    __shared__ float b2s, eT;
    const int t = threadIdx.x;
    if (t < 192) w1s[t] = fw1[t];
    if (t < 64) { b1s[t] = fb1[t]; w2s[t] = fw2[t]; }
    if (t == 0) { b2s = fb2[0]; eT = expf(temp[0]); }
    __syncthreads();

    size_t idx = (size_t)blockIdx.x * 256 + t;
    int b = (int)(idx >> 14);       // N_C = 2^14
    int n = (int)(idx & (N_C - 1));

    float s = S[idx];
    float cosv = s * qinv[b] * kinv[n] * eT;
    float d2 = qsq[b] + ksq[n] - 2.f * s;
    float euc = 1.f / (1.f + sqrtf(fmaxf(d2, 0.f)));
    float ls = 0.f;
    #pragma unroll
    for (int h = 0; h < NH; h++) {
        int r = h * B_Q + b;
        ls += expf(scores[(size_t)h * B_Q * N_C + idx] - m[r]) / l[r];
    }
    float learned = ls * (1.f / NH);

    float o = b2s;
    #pragma unroll
    for (int j = 0; j < 64; j++) {
        float hv = fmaf(cosv, w1s[j],
                   fmaf(euc, w1s[64 + j],
                   fmaf(learned, w1s[128 + j], b1s[j])));
        o = fmaf(fmaxf(hv, 0.f), w2s[j], o);
    }
    out[idx] = 1.f / (1.f + expf(-o));
}

// ---------------- launch ----------------
extern "C" void kernel_launch(void* const* d_in, const int* in_sizes, int n_in,
                              void* d_out, int out_size)
{
    (void)in_sizes; (void)n_in; (void)out_size;
    const float* qf   = (const float*)d_in[0];
    const float* cf   = (const float*)d_in[1];
    const float* temp = (const float*)d_in[2];
    const float* q_w1 = (const float*)d_in[3];
    const float* q_b1 = (const float*)d_in[4];
    const float* q_g  = (const float*)d_in[5];
    const float* q_be = (const float*)d_in[6];
    const float* q_w2 = (const float*)d_in[7];
    const float* q_b2 = (const float*)d_in[8];
    const float* k_w1 = (const float*)d_in[9];
    const float* k_b1 = (const float*)d_in[10];
    const float* k_g  = (const float*)d_in[11];
    const float* k_be = (const float*)d_in[12];
    const float* k_w2 = (const float*)d_in[13];
    const float* k_b2 = (const float*)d_in[14];
    const float* wq   = (const float*)d_in[15];
    const float* bq   = (const float*)d_in[16];
    const float* wk   = (const float*)d_in[17];
    const float* bk   = (const float*)d_in[18];
    const float* fw1  = (const float*)d_in[19];
    const float* fb1  = (const float*)d_in[20];
    const float* fw2  = (const float*)d_in[21];
    const float* fb2  = (const float*)d_in[22];
    float* out = (float*)d_out;

    float *bufA, *bufB, *S, *scores, *Tq, *Hq, *qp, *qh;
    float *qsq, *qinv, *ksq, *kinv, *mm, *ll;
    cudaGetSymbolAddress((void**)&bufA, g_bufA);
    cudaGetSymbolAddress((void**)&bufB, g_bufB);
    cudaGetSymbolAddress((void**)&S, g_S);
    cudaGetSymbolAddress((void**)&scores, g_scores);
    cudaGetSymbolAddress((void**)&Tq, g_Tq);
    cudaGetSymbolAddress((void**)&Hq, g_Hq);
    cudaGetSymbolAddress((void**)&qp, g_qp);
    cudaGetSymbolAddress((void**)&qh, g_qh);
    cudaGetSymbolAddress((void**)&qsq, g_qsq);
    cudaGetSymbolAddress((void**)&qinv, g_qinv);
    cudaGetSymbolAddress((void**)&ksq, g_ksq);
    cudaGetSymbolAddress((void**)&kinv, g_kinv);
    cudaGetSymbolAddress((void**)&mm, g_m);
    cudaGetSymbolAddress((void**)&ll, g_l);

    const dim3 gK(D_M / 128, N_C / 128);  // (8, 128) big [N_C x D_M] gemms
    const dim3 gQ(D_M / 128, B_Q / 128);  // (8, 8)

    // candidate projection: Tk(bufA) -> Hk(bufB) -> kp(bufA)
    gemm_nn<true><<<gK, 256>>>(cf, k_w1, k_b1, bufA, N_C, D_M, D_M);
    ln_gelu<<<N_C, 256>>>(bufA, k_g, k_be, bufB);
    gemm_nn<true><<<gK, 256>>>(bufB, k_w2, k_b2, bufA, N_C, D_M, D_M);

    // query projection: Tq -> Hq -> qp
    gemm_nn<true><<<gQ, 256>>>(qf, q_w1, q_b1, Tq, B_Q, D_M, D_M);
    ln_gelu<<<B_Q, 256>>>(Tq, q_g, q_be, Hq);
    gemm_nn<true><<<gQ, 256>>>(Hq, q_w2, q_b2, qp, B_Q, D_M, D_M);

    // norms
    row_stats<<<B_Q, 256>>>(qp, qsq, qinv);
    row_stats<<<N_C, 256>>>(bufA, ksq, kinv);

    // S = qp @ kp^T
    gemm_nt<<<dim3(N_C / 128, B_Q / 128, 1), 256>>>(
        qp, bufA, S, B_Q, N_C, D_M, D_M, D_M, 1.f, 0, 0, 0);

    // MHA in-projections: qh, kh(bufB)
    gemm_nn<true><<<gQ, 256>>>(qp, wq, bq, qh, B_Q, D_M, D_M);
    gemm_nn<true><<<gK, 256>>>(bufA, wk, bk, bufB, N_C, D_M, D_M);

    // per-head scores: [H][B][N], scaled by 1/sqrt(HD)
    gemm_nt<<<dim3(N_C / 128, B_Q / 128, NH), 256>>>(
        qh, bufB, scores, B_Q, N_C, HDIM, D_M, D_M,
        0.08838834764831845f, HDIM, HDIM, (size_t)B_Q * N_C);

    // softmax normalizers
    softmax_stats<<<NH * B_Q, 256>>>(scores, mm, ll);

    // fused epilogue
    fuse<<<(unsigned)((size_t)B_Q * N_C / 256), 256>>>(
        S, scores, qsq, qinv, ksq, kinv, mm, ll, temp,
        fw1, fb1, fw2, fb2, out);
}

// round 4
// speedup vs baseline: 2.9533x; 2.9533x over previous
#include <cuda_runtime.h>
#include <cuda_bf16.h>
#include <math.h>
#include <stdint.h>
#include <stddef.h>

#define B_Q 1024
#define N_C 16384
#define D_M 1024
#define NH  8
#define HDIM 128
typedef __nv_bfloat16 bf16;

// ---------------- static scratch ----------------
__device__ bf16  g_wth[(size_t)6 * D_M * D_M], g_wtl[(size_t)6 * D_M * D_M];
__device__ bf16  g_cfh[(size_t)N_C * D_M], g_cfl[(size_t)N_C * D_M];
__device__ bf16  g_qfh[(size_t)B_Q * D_M], g_qfl[(size_t)B_Q * D_M];
__device__ float g_T[(size_t)N_C * D_M];
__device__ bf16  g_Hh[(size_t)N_C * D_M], g_Hl[(size_t)N_C * D_M];
__device__ bf16  g_kph[(size_t)N_C * D_M], g_kpl[(size_t)N_C * D_M];
__device__ bf16  g_qph[(size_t)B_Q * D_M], g_qpl[(size_t)B_Q * D_M];
__device__ bf16  g_kh[(size_t)N_C * D_M];
__device__ bf16  g_qh[(size_t)B_Q * D_M];
__device__ float g_S[(size_t)B_Q * N_C];
__device__ bf16  g_sc[(size_t)NH * B_Q * N_C];
__device__ float g_qsq[B_Q], g_qinv[B_Q], g_ksq[N_C], g_kinv[N_C];
__device__ float g_m[NH * B_Q], g_linv[NH * B_Q];

// ---------------- PTX helpers ----------------
__device__ __forceinline__ uint32_t smem_u32(const void* p) {
    uint32_t a;
    asm("{ .reg .u64 t; cvta.to.shared.u64 t, %1; cvt.u32.u64 %0, t; }" : "=r"(a) : "l"(p));
    return a;
}
__device__ __forceinline__ void cp16(uint32_t dst, const void* src) {
    asm volatile("cp.async.cg.shared.global [%0], [%1], 16;" :: "r"(dst), "l"(src));
}
__device__ __forceinline__ void cp_commit() {
    asm volatile("cp.async.commit_group;" ::: "memory");
}
__device__ __forceinline__ void cp_wait1() {
    asm volatile("cp.async.wait_group 1;" ::: "memory");
}
__device__ __forceinline__ void cp_wait0() {
    asm volatile("cp.async.wait_group 0;" ::: "memory");
}
__device__ __forceinline__ void ldsm4(uint32_t a[4], uint32_t addr) {
    asm volatile("ldmatrix.sync.aligned.m8n8.x4.shared.b16 {%0,%1,%2,%3}, [%4];"
                 : "=r"(a[0]), "=r"(a[1]), "=r"(a[2]), "=r"(a[3]) : "r"(addr));
}
__device__ __forceinline__ void mma16816(float c[4], const uint32_t a[4], const uint32_t b[2]) {
    asm volatile(
        "mma.sync.aligned.m16n8k16.row.col.f32.bf16.bf16.f32 "
        "{%0,%1,%2,%3}, {%4,%5,%6,%7}, {%8,%9}, {%0,%1,%2,%3};"
        : "+f"(c[0]), "+f"(c[1]), "+f"(c[2]), "+f"(c[3])
        : "r"(a[0]), "r"(a[1]), "r"(a[2]), "r"(a[3]), "r"(b[0]), "r"(b[1]));
}

// ---------------- mma.sync GEMM: C[M,N] = alpha*(A@B^T)+bias ----------------
// A[M,K], B[N,K] bf16 K-major (leading dims lda/ldb elements).
// NPASS: 3 = hi/lo split (acc += Ah*Bh + Al*Bh + Ah*Bl), 1 = hi only.
// OUT: 0 = f32, 2 = bf16 hi/lo pair, 3 = single bf16.
// blockIdx.z: A += z*a_zoff, B += z*b_zoff, C += z*c_zoff.
template <int NPASS, int OUT, bool BIAS>
__global__ __launch_bounds__(256)
void gemm_mma(const bf16* __restrict__ Ah, const bf16* __restrict__ Al,
              const bf16* __restrict__ Bh, const bf16* __restrict__ Bl,
              const float* __restrict__ bias, float* __restrict__ Cf,
              bf16* __restrict__ Ch, bf16* __restrict__ Cl,
              int K, int lda, int ldb, int ldc, float alpha,
              int a_zoff, int b_zoff, long long c_zoff)
{
    constexpr uint32_t APART = 8192u;                       // 128 rows * 64B
    constexpr uint32_t BOFF  = (NPASS == 3) ? 16384u : 8192u;
    constexpr uint32_t STAGE = (NPASS == 3) ? 32768u : 16384u;

    extern __shared__ __align__(1024) char dsm[];
    const uint32_t sb = smem_u32(dsm);

    const int t = threadIdx.x, lane = t & 31, warp = t >> 5;
    const int warp_m = (warp >> 2) * 64;     // 0 or 64
    const int warp_n = (warp & 3) * 32;      // 0,32,64,96
    const int m0 = blockIdx.y * 128, n0 = blockIdx.x * 128, z = blockIdx.z;
    Ah += (size_t)z * a_zoff; Bh += (size_t)z * b_zoff;
    if (NPASS == 3) { Al += (size_t)z * a_zoff; Bl += (size_t)z * b_zoff; }
    if (OUT == 0) Cf += (size_t)z * c_zoff;
    else { Ch += (size_t)z * c_zoff; if (OUT == 2) Cl += (size_t)z * c_zoff; }

    float acc[4][4][4];
    #pragma unroll
    for (int i = 0; i < 4; i++)
        #pragma unroll
        for (int j = 0; j < 4; j++)
            #pragma unroll
            for (int k = 0; k < 4; k++) acc[i][j][k] = 0.f;

    const int nch = K >> 5;  // BK = 32

    auto load_chunk = [&](int stage, int k0) {
        const uint32_t stb = sb + (uint32_t)stage * STAGE;
        #pragma unroll
        for (int i = 0; i < 2; i++) {       // A: 512 16B chunks
            int idx = t + i * 256;
            int r = idx >> 2, c = idx & 3;
            uint32_t off = (uint32_t)(r * 64 + ((c ^ (r & 3)) * 16));
            size_t go = (size_t)(m0 + r) * lda + k0 + c * 8;
            cp16(stb + off, Ah + go);
            if (NPASS == 3) cp16(stb + APART + off, Al + go);
        }
        #pragma unroll
        for (int i = 0; i < 2; i++) {       // B
            int idx = t + i * 256;
            int r = idx >> 2, c = idx & 3;
            uint32_t off = (uint32_t)(r * 64 + ((c ^ (r & 3)) * 16));
            size_t go = (size_t)(n0 + r) * ldb + k0 + c * 8;
            cp16(stb + BOFF + off, Bh + go);
            if (NPASS == 3) cp16(stb + BOFF + APART + off, Bl + go);
        }
        cp_commit();
    };

    // per-lane ldmatrix address pieces
    const int a_row = (lane & 15);          // + warp_m + mt*16
    const int a_kh  = lane >> 4;            // k half
    const int b_row = (lane >> 4) * 8 + (lane & 7);  // + warp_n + pair*16
    const int b_kh  = (lane >> 3) & 1;

    load_chunk(0, 0);
    if (nch > 1) load_chunk(1, 32);

    for (int i = 0; i < nch; i++) {
        if (i + 1 < nch) cp_wait1(); else cp_wait0();
        __syncthreads();
        const uint32_t stb = sb + (uint32_t)(i % 3) * STAGE;
        if (i + 2 < nch) load_chunk((i + 2) % 3, (i + 2) << 5);

        #pragma unroll
        for (int ks = 0; ks < 2; ks++) {
            uint32_t fa[4][4], fb[2][4];
            #pragma unroll
            for (int mt = 0; mt < 4; mt++) {
                int r = warp_m + mt * 16 + a_row;
                int c = ks * 2 + a_kh;
                ldsm4(fa[mt], stb + (uint32_t)(r * 64 + ((c ^ (r & 3)) * 16)));
            }
            #pragma unroll
            for (int pr = 0; pr < 2; pr++) {
                int r = warp_n + pr * 16 + b_row;
                int c = ks * 2 + b_kh;
                ldsm4(fb[pr], stb + BOFF + (uint32_t)(r * 64 + ((c ^ (r & 3)) * 16)));
            }
            #pragma unroll
            for (int mt = 0; mt < 4; mt++)
                #pragma unroll
                for (int nt = 0; nt < 4; nt++)
                    mma16816(acc[mt][nt], fa[mt], &fb[nt >> 1][(nt & 1) * 2]);

            if (NPASS == 3) {
                uint32_t fa2[4][4];
                #pragma unroll
                for (int mt = 0; mt < 4; mt++) {
                    int r = warp_m + mt * 16 + a_row;
                    int c = ks * 2 + a_kh;
                    ldsm4(fa2[mt], stb + APART + (uint32_t)(r * 64 + ((c ^ (r & 3)) * 16)));
                }
                #pragma unroll
                for (int mt = 0; mt < 4; mt++)
                    #pragma unroll
                    for (int nt = 0; nt < 4; nt++)
                        mma16816(acc[mt][nt], fa2[mt], &fb[nt >> 1][(nt & 1) * 2]);
                #pragma unroll
                for (int pr = 0; pr < 2; pr++) {
                    int r = warp_n + pr * 16 + b_row;
                    int c = ks * 2 + b_kh;
                    ldsm4(fb[pr], stb + BOFF + APART + (uint32_t)(r * 64 + ((c ^ (r & 3)) * 16)));
                }
                #pragma unroll
                for (int mt = 0; mt < 4; mt++)
                    #pragma unroll
                    for (int nt = 0; nt < 4; nt++)
                        mma16816(acc[mt][nt], fa[mt], &fb[nt >> 1][(nt & 1) * 2]);
            }
        }
        __syncthreads();
    }

    // ---- epilogue ----
    #pragma unroll
    for (int mt = 0; mt < 4; mt++) {
        #pragma unroll
        for (int half = 0; half < 2; half++) {
            const int gr = m0 + warp_m + mt * 16 + (lane >> 2) + half * 8;
            #pragma unroll
            for (int nt = 0; nt < 4; nt++) {
                const int gc = n0 + warp_n + nt * 8 + 2 * (lane & 3);
                float v0 = acc[mt][nt][half * 2 + 0] * alpha;
                float v1 = acc[mt][nt][half * 2 + 1] * alpha;
                if (BIAS) { v0 += bias[gc]; v1 += bias[gc + 1]; }
                size_t o = (size_t)gr * ldc + gc;
                if (OUT == 0) {
                    *(float2*)(Cf + o) = make_float2(v0, v1);
                } else if (OUT == 2) {
                    bf16 h0 = __float2bfloat16(v0), h1 = __float2bfloat16(v1);
                    bf16 l0 = __float2bfloat16(v0 - __bfloat162float(h0));
                    bf16 l1 = __float2bfloat16(v1 - __bfloat162float(h1));
                    *(__nv_bfloat162*)(Ch + o) = __halves2bfloat162(h0, h1);
                    *(__nv_bfloat162*)(Cl + o) = __halves2bfloat162(l0, l1);
                } else {
                    *(__nv_bfloat162*)(Ch + o) = __floats2bfloat162_rn(v0, v1);
                }
            }
        }
    }
}

// ---------------- reductions ----------------
__device__ __forceinline__ float blockReduceSum(float v) {
    __shared__ float sh[32];
    int lane = threadIdx.x & 31, w = threadIdx.x >> 5;
    #pragma unroll
    for (int o = 16; o > 0; o >>= 1) v += __shfl_down_sync(0xffffffffu, v, o);
    __syncthreads();
    if (lane == 0) sh[w] = v;
    __syncthreads();
    float r = 0.f;
    if (threadIdx.x < (blockDim.x >> 5)) r = sh[threadIdx.x];
    if (w == 0) {
        #pragma unroll
        for (int o = 4; o > 0; o >>= 1) r += __shfl_down_sync(0xffffffffu, r, o);
    }
    if (threadIdx.x == 0) sh[0] = r;
    __syncthreads();
    return sh[0];
}
__device__ __forceinline__ float blockReduceMax(float v) {
    __shared__ float sh[32];
    int lane = threadIdx.x & 31, w = threadIdx.x >> 5;
    #pragma unroll
    for (int o = 16; o > 0; o >>= 1) v = fmaxf(v, __shfl_down_sync(0xffffffffu, v, o));
    __syncthreads();
    if (lane == 0) sh[w] = v;
    __syncthreads();
    float r = -INFINITY;
    if (threadIdx.x < (blockDim.x >> 5)) r = sh[threadIdx.x];
    if (w == 0) {
        #pragma unroll
        for (int o = 4; o > 0; o >>= 1) r = fmaxf(r, __shfl_down_sync(0xffffffffu, r, o));
    }
    if (threadIdx.x == 0) sh[0] = r;
    __syncthreads();
    return sh[0];
}

// ---------------- elementwise ----------------
__global__ void convert_split(const float* __restrict__ X, bf16* __restrict__ H,
                              bf16* __restrict__ L)
{
    size_t i = ((size_t)blockIdx.x * 256 + threadIdx.x) * 4;
    float4 v = *(const float4*)(X + i);
    float vv[4] = {v.x, v.y, v.z, v.w};
    #pragma unroll
    for (int k = 0; k < 4; k++) {
        bf16 h = __float2bfloat16(vv[k]);
        H[i + k] = h;
        L[i + k] = __float2bfloat16(vv[k] - __bfloat162float(h));
    }
}

__global__ void transpose_split(const float* __restrict__ W, bf16* __restrict__ Th,
                                bf16* __restrict__ Tl)
{
    __shared__ float tile[32][33];
    int x = blockIdx.x * 32 + threadIdx.x, y0 = blockIdx.y * 32;
    #pragma unroll
    for (int i = 0; i < 32; i += 8)
        tile[threadIdx.y + i][threadIdx.x] = W[(size_t)(y0 + threadIdx.y + i) * D_M + x];
    __syncthreads();
    int k = y0 + threadIdx.x;
    #pragma unroll
    for (int i = 0; i < 32; i += 8) {
        int n = blockIdx.x * 32 + threadIdx.y + i;
        float v = tile[threadIdx.x][threadIdx.y + i];
        bf16 h = __float2bfloat16(v);
        Th[(size_t)n * D_M + k] = h;
        Tl[(size_t)n * D_M + k] = __float2bfloat16(v - __bfloat162float(h));
    }
}

__global__ void ln_gelu_split(const float* __restrict__ X, const float* __restrict__ g,
                              const float* __restrict__ be, bf16* __restrict__ Yh,
                              bf16* __restrict__ Yl)
{
    const int row = blockIdx.x;
    const float* x = X + (size_t)row * D_M;
    float xv[4];
    #pragma unroll
    for (int i = 0; i < 4; i++) xv[i] = x[threadIdx.x + i * 256];
    float mu = blockReduceSum(xv[0] + xv[1] + xv[2] + xv[3]) * (1.f / D_M);
    float vs = 0.f;
    #pragma unroll
    for (int i = 0; i < 4; i++) { float d = xv[i] - mu; vs += d * d; }
    float rstd = rsqrtf(blockReduceSum(vs) * (1.f / D_M) + 1e-5f);
    #pragma unroll
    for (int i = 0; i < 4; i++) {
        int c = threadIdx.x + i * 256;
        float y = (xv[i] - mu) * rstd * g[c] + be[c];
        float o = y * 0.5f * (1.f + erff(y * 0.70710678118654752f));
        bf16 h = __float2bfloat16(o);
        Yh[(size_t)row * D_M + c] = h;
        Yl[(size_t)row * D_M + c] = __float2bfloat16(o - __bfloat162float(h));
    }
}

__global__ void row_stats_split(const bf16* __restrict__ H, const bf16* __restrict__ L,
                                float* __restrict__ sq, float* __restrict__ inv)
{
    const int row = blockIdx.x;
    float s = 0.f;
    for (int i = threadIdx.x; i < D_M; i += 256) {
        float v = __bfloat162float(H[(size_t)row * D_M + i]) +
                  __bfloat162float(L[(size_t)row * D_M + i]);
        s = fmaf(v, v, s);
    }
    float tot = blockReduceSum(s);
    if (threadIdx.x == 0) { sq[row] = tot; inv[row] = rsqrtf(tot); }
}

__global__ void softmax_stats(const bf16* __restrict__ Sc, float* __restrict__ m,
                              float* __restrict__ linv)
{
    const int r = blockIdx.x;
    const bf16* x = Sc + (size_t)r * N_C;
    float mx = -INFINITY;
    for (int i = threadIdx.x; i < N_C; i += 256)
        mx = fmaxf(mx, __bfloat162float(x[i]));
    mx = blockReduceMax(mx);
    float s = 0.f;
    for (int i = threadIdx.x; i < N_C; i += 256)
        s += __expf(__bfloat162float(x[i]) - mx);
    float tot = blockReduceSum(s);
    if (threadIdx.x == 0) { m[r] = mx; linv[r] = 1.f / tot; }
}

__global__ __launch_bounds__(256)
void fuse(const float* __restrict__ S, const bf16* __restrict__ scores,
          const float* __restrict__ qsq, const float* __restrict__ qinv,
          const float* __restrict__ ksq, const float* __restrict__ kinv,
          const float* __restrict__ m, const float* __restrict__ linv,
          const float* __restrict__ temp,
          const float* __restrict__ fw1, const float* __restrict__ fb1,
          const float* __restrict__ fw2, const float* __restrict__ fb2,
          float* __restrict__ out)
{
    __shared__ float w1s[192], b1s[64], w2s[64], b2s, eT;
    const int t = threadIdx.x;
    if (t < 192) w1s[t] = fw1[t];
    if (t < 64) { b1s[t] = fb1[t]; w2s[t] = fw2[t]; }
    if (t == 0) { b2s = fb2[0]; eT = expf(temp[0]); }
    __syncthreads();

    size_t idx = (size_t)blockIdx.x * 256 + t;
    int b = (int)(idx >> 14), n = (int)(idx & (N_C - 1));

    float s = S[idx];
    float cosv = s * qinv[b] * kinv[n] * eT;
    float d2 = qsq[b] + ksq[n] - 2.f * s;
    float euc = 1.f / (1.f + sqrtf(fmaxf(d2, 0.f)));
    float ls = 0.f;
    #pragma unroll
    for (int h = 0; h < NH; h++) {
        int r = h * B_Q + b;
        ls += __expf(__bfloat162float(scores[(size_t)h * B_Q * N_C + idx]) - m[r]) * linv[r];
    }
    float learned = ls * (1.f / NH);

    float o = b2s;
    #pragma unroll
    for (int j = 0; j < 64; j++) {
        float hv = fmaf(cosv, w1s[j], fmaf(euc, w1s[64 + j],
                   fmaf(learned, w1s[128 + j], b1s[j])));
        o = fmaf(fmaxf(hv, 0.f), w2s[j], o);
    }
    out[idx] = 1.f / (1.f + __expf(-o));
}

// ---------------- launch ----------------
#define SMEM3 (3 * 32768)
#define SMEM1 (3 * 16384)

extern "C" void kernel_launch(void* const* d_in, const int* in_sizes, int n_in,
                              void* d_out, int out_size)
{
    (void)in_sizes; (void)n_in; (void)out_size;
    const float* qf   = (const float*)d_in[0];
    const float* cf   = (const float*)d_in[1];
    const float* temp = (const float*)d_in[2];
    const float* q_w1 = (const float*)d_in[3];
    const float* q_b1 = (const float*)d_in[4];
    const float* q_g  = (const float*)d_in[5];
    const float* q_be = (const float*)d_in[6];
    const float* q_w2 = (const float*)d_in[7];
    const float* q_b2 = (const float*)d_in[8];
    const float* k_w1 = (const float*)d_in[9];
    const float* k_b1 = (const float*)d_in[10];
    const float* k_g  = (const float*)d_in[11];
    const float* k_be = (const float*)d_in[12];
    const float* k_w2 = (const float*)d_in[13];
    const float* k_b2 = (const float*)d_in[14];
    const float* wq   = (const float*)d_in[15];
    const float* bq   = (const float*)d_in[16];
    const float* wk   = (const float*)d_in[17];
    const float* bk   = (const float*)d_in[18];
    const float* fw1  = (const float*)d_in[19];
    const float* fb1  = (const float*)d_in[20];
    const float* fw2  = (const float*)d_in[21];
    const float* fb2  = (const float*)d_in[22];
    float* out = (float*)d_out;

    bf16 *wth, *wtl, *cfh, *cfl, *qfh, *qfl, *Hh, *Hl;
    bf16 *kph, *kpl, *qph, *qpl, *kh, *qh, *sc;
    float *T, *S, *qsq, *qinv, *ksq, *kinv, *mm, *linv;
    cudaGetSymbolAddress((void**)&wth, g_wth);
    cudaGetSymbolAddress((void**)&wtl, g_wtl);
    cudaGetSymbolAddress((void**)&cfh, g_cfh);
    cudaGetSymbolAddress((void**)&cfl, g_cfl);
    cudaGetSymbolAddress((void**)&qfh, g_qfh);
    cudaGetSymbolAddress((void**)&qfl, g_qfl);
    cudaGetSymbolAddress((void**)&T,   g_T);
    cudaGetSymbolAddress((void**)&Hh,  g_Hh);
    cudaGetSymbolAddress((void**)&Hl,  g_Hl);
    cudaGetSymbolAddress((void**)&kph, g_kph);
    cudaGetSymbolAddress((void**)&kpl, g_kpl);
    cudaGetSymbolAddress((void**)&qph, g_qph);
    cudaGetSymbolAddress((void**)&qpl, g_qpl);
    cudaGetSymbolAddress((void**)&kh,  g_kh);
    cudaGetSymbolAddress((void**)&qh,  g_qh);
    cudaGetSymbolAddress((void**)&S,   g_S);
    cudaGetSymbolAddress((void**)&sc,  g_sc);
    cudaGetSymbolAddress((void**)&qsq, g_qsq);
    cudaGetSymbolAddress((void**)&qinv, g_qinv);
    cudaGetSymbolAddress((void**)&ksq, g_ksq);
    cudaGetSymbolAddress((void**)&kinv, g_kinv);
    cudaGetSymbolAddress((void**)&mm,  g_m);
    cudaGetSymbolAddress((void**)&linv, g_linv);

    cudaFuncSetAttribute(gemm_mma<3, 0, true>,  cudaFuncAttributeMaxDynamicSharedMemorySize, SMEM3);
    cudaFuncSetAttribute(gemm_mma<3, 2, true>,  cudaFuncAttributeMaxDynamicSharedMemorySize, SMEM3);
    cudaFuncSetAttribute(gemm_mma<3, 0, false>, cudaFuncAttributeMaxDynamicSharedMemorySize, SMEM3);
    cudaFuncSetAttribute(gemm_mma<1, 3, true>,  cudaFuncAttributeMaxDynamicSharedMemorySize, SMEM1);
    cudaFuncSetAttribute(gemm_mma<1, 3, false>, cudaFuncAttributeMaxDynamicSharedMemorySize, SMEM1);

    const size_t DD = (size_t)D_M * D_M;
    dim3 tgrid(D_M / 32, D_M / 32), tblk(32, 8);
    transpose_split<<<tgrid, tblk>>>(k_w1, wth + 0 * DD, wtl + 0 * DD);
    transpose_split<<<tgrid, tblk>>>(k_w2, wth + 1 * DD, wtl + 1 * DD);
    transpose_split<<<tgrid, tblk>>>(wk,   wth + 2 * DD, wtl + 2 * DD);
    transpose_split<<<tgrid, tblk>>>(q_w1, wth + 3 * DD, wtl + 3 * DD);
    transpose_split<<<tgrid, tblk>>>(q_w2, wth + 4 * DD, wtl + 4 * DD);
    transpose_split<<<tgrid, tblk>>>(wq,   wth + 5 * DD, wtl + 5 * DD);
    convert_split<<<(unsigned)((size_t)N_C * D_M / 1024), 256>>>(cf, cfh, cfl);
    convert_split<<<(unsigned)((size_t)B_Q * D_M / 1024), 256>>>(qf, qfh, qfl);

    const dim3 gK(D_M / 128, N_C / 128);   // (8, 128)
    const dim3 gQ(D_M / 128, B_Q / 128);   // (8, 8)

    // K path: Tk -> Hk -> kp(split) -> kh(bf16)
    gemm_mma<3, 0, true><<<gK, 256, SMEM3>>>(cfh, cfl, wth + 0 * DD, wtl + 0 * DD,
        k_b1, T, 0, 0, D_M, D_M, D_M, D_M, 1.f, 0, 0, 0);
    ln_gelu_split<<<N_C, 256>>>(T, k_g, k_be, Hh, Hl);
    gemm_mma<3, 2, true><<<gK, 256, SMEM3>>>(Hh, Hl, wth + 1 * DD, wtl + 1 * DD,
        k_b2, 0, kph, kpl, D_M, D_M, D_M, D_M, 1.f, 0, 0, 0);
    row_stats_split<<<N_C, 256>>>(kph, kpl, ksq, kinv);
    gemm_mma<1, 3, true><<<gK, 256, SMEM1>>>(kph, 0, wth + 2 * DD, 0,
        bk, 0, kh, 0, D_M, D_M, D_M, D_M, 1.f, 0, 0, 0);

    // Q path
    gemm_mma<3, 0, true><<<gQ, 256, SMEM3>>>(qfh, qfl, wth + 3 * DD, wtl + 3 * DD,
        q_b1, T, 0, 0, D_M, D_M, D_M, D_M, 1.f, 0, 0, 0);
    ln_gelu_split<<<B_Q, 256>>>(T, q_g, q_be, Hh, Hl);
    gemm_mma<3, 2, true><<<gQ, 256, SMEM3>>>(Hh, Hl, wth + 4 * DD, wtl + 4 * DD,
        q_b2, 0, qph, qpl, D_M, D_M, D_M, D_M, 1.f, 0, 0, 0);
    row_stats_split<<<B_Q, 256>>>(qph, qpl, qsq, qinv);
    gemm_mma<1, 3, true><<<gQ, 256, SMEM1>>>(qph, 0, wth + 5 * DD, 0,
        bq, 0, qh, 0, D_M, D_M, D_M, D_M, 1.f, 0, 0, 0);

    // S = qp @ kp^T (f32, split inputs)
    gemm_mma<3, 0, false><<<dim3(N_C / 128, B_Q / 128), 256, SMEM3>>>(
        qph, qpl, kph, kpl, 0, S, 0, 0, D_M, D_M, D_M, N_C, 1.f, 0, 0, 0);

    // per-head scores (bf16), z = head
    gemm_mma<1, 3, false><<<dim3(N_C / 128, B_Q / 128, NH), 256, SMEM1>>>(
        qh, 0, kh, 0, 0, 0, sc, 0, HDIM, D_M, D_M, N_C,
        0.08838834764831845f, HDIM, HDIM, (long long)B_Q * N_C);

    softmax_stats<<<NH * B_Q, 256>>>(sc, mm, linv);
    fuse<<<(unsigned)((size_t)B_Q * N_C / 256), 256>>>(
        S, sc, qsq, qinv, ksq, kinv, mm, linv, temp, fw1, fb1, fw2, fb2, out);
}

// round 5
// speedup vs baseline: 3.3265x; 1.1263x over previous
#include <cuda_runtime.h>
#include <cuda_bf16.h>
#include <math.h>
#include <stdint.h>
#include <stddef.h>

#define B_Q 1024
#define N_C 16384
#define D_M 1024
#define NH  8
#define HDIM 128
typedef __nv_bfloat16 bf16;

// ---------------- static scratch ----------------
__device__ bf16  g_wth[(size_t)6 * D_M * D_M], g_wtl[(size_t)6 * D_M * D_M];
__device__ bf16  g_cfh[(size_t)N_C * D_M], g_cfl[(size_t)N_C * D_M];
__device__ bf16  g_qfh[(size_t)B_Q * D_M], g_qfl[(size_t)B_Q * D_M];
__device__ float g_T[(size_t)N_C * D_M];
__device__ bf16  g_Hh[(size_t)N_C * D_M], g_Hl[(size_t)N_C * D_M];
__device__ bf16  g_kph[(size_t)N_C * D_M], g_kpl[(size_t)N_C * D_M];
__device__ bf16  g_qph[(size_t)B_Q * D_M], g_qpl[(size_t)B_Q * D_M];
__device__ bf16  g_kh[(size_t)N_C * D_M];
__device__ bf16  g_qh[(size_t)B_Q * D_M];
__device__ float g_S[(size_t)B_Q * N_C];
__device__ bf16  g_sc[(size_t)NH * B_Q * N_C];
__device__ float g_qsq[B_Q], g_qinv[B_Q], g_ksq[N_C], g_kinv[N_C];
__device__ float g_m[NH * B_Q], g_linv[NH * B_Q];

// ---------------- PTX helpers ----------------
__device__ __forceinline__ uint32_t smem_u32(const void* p) {
    uint32_t a;
    asm("{ .reg .u64 t; cvta.to.shared.u64 t, %1; cvt.u32.u64 %0, t; }" : "=r"(a) : "l"(p));
    return a;
}
__device__ __forceinline__ void cp16(uint32_t dst, const void* src) {
    asm volatile("cp.async.cg.shared.global [%0], [%1], 16;" :: "r"(dst), "l"(src));
}
__device__ __forceinline__ void cp_commit() {
    asm volatile("cp.async.commit_group;" ::: "memory");
}
template <int N>
__device__ __forceinline__ void cp_wait() {
    if constexpr (N == 0) asm volatile("cp.async.wait_group 0;" ::: "memory");
    else if constexpr (N == 1) asm volatile("cp.async.wait_group 1;" ::: "memory");
    else asm volatile("cp.async.wait_group 2;" ::: "memory");
}
__device__ __forceinline__ void ldsm4(uint32_t a[4], uint32_t addr) {
    asm volatile("ldmatrix.sync.aligned.m8n8.x4.shared.b16 {%0,%1,%2,%3}, [%4];"
                 : "=r"(a[0]), "=r"(a[1]), "=r"(a[2]), "=r"(a[3]) : "r"(addr));
}
__device__ __forceinline__ void mma16816(float c[4], const uint32_t a[4], const uint32_t b[2]) {
    asm volatile(
        "mma.sync.aligned.m16n8k16.row.col.f32.bf16.bf16.f32 "
        "{%0,%1,%2,%3}, {%4,%5,%6,%7}, {%8,%9}, {%0,%1,%2,%3};"
        : "+f"(c[0]), "+f"(c[1]), "+f"(c[2]), "+f"(c[3])
        : "r"(a[0]), "r"(a[1]), "r"(a[2]), "r"(a[3]), "r"(b[0]), "r"(b[1]));
}

// SW128 swizzled smem offset: 128 rows of 128B, conflict-free for ldmatrix + cp.async
__device__ __forceinline__ uint32_t swz(int r, int c) {
    return (uint32_t)(r * 128 + ((c ^ (r & 7)) * 16));
}

// ---------------- mma.sync GEMM: C[M,N] = alpha*(A@B^T)+bias ----------------
// A[M,K], B[N,K] bf16 K-major. BK=64. NPASS: 3 = hi/lo split, 1 = hi only.
// OUT: 0 = f32, 2 = bf16 hi/lo pair, 3 = single bf16.
template <int NPASS, int OUT, bool BIAS, int NSTAGE>
__global__ __launch_bounds__(256)
void gemm_mma(const bf16* __restrict__ Ah, const bf16* __restrict__ Al,
              const bf16* __restrict__ Bh, const bf16* __restrict__ Bl,
              const float* __restrict__ bias, float* __restrict__ Cf,
              bf16* __restrict__ Ch, bf16* __restrict__ Cl,
              int K, int lda, int ldb, int ldc, float alpha,
              int a_zoff, int b_zoff, long long c_zoff)
{
    constexpr uint32_t APART = 16384u;                       // 128 rows * 128B
    constexpr uint32_t BOFF  = (NPASS == 3) ? 32768u : 16384u;
    constexpr uint32_t STAGE = (NPASS == 3) ? 65536u : 32768u;

    extern __shared__ __align__(1024) char dsm[];
    const uint32_t sb = smem_u32(dsm);

    const int t = threadIdx.x, lane = t & 31, warp = t >> 5;
    const int warp_m = (warp >> 2) * 64;     // 0 or 64
    const int warp_n = (warp & 3) * 32;      // 0,32,64,96
    const int m0 = blockIdx.y * 128, n0 = blockIdx.x * 128, z = blockIdx.z;
    Ah += (size_t)z * a_zoff; Bh += (size_t)z * b_zoff;
    if (NPASS == 3) { Al += (size_t)z * a_zoff; Bl += (size_t)z * b_zoff; }
    if (OUT == 0) Cf += (size_t)z * c_zoff;
    else { Ch += (size_t)z * c_zoff; if (OUT == 2) Cl += (size_t)z * c_zoff; }

    float acc[4][4][4];
    #pragma unroll
    for (int i = 0; i < 4; i++)
        #pragma unroll
        for (int j = 0; j < 4; j++)
            #pragma unroll
            for (int k = 0; k < 4; k++) acc[i][j][k] = 0.f;

    const int nch = K >> 6;  // BK = 64

    auto load_chunk = [&](int stage, int k0) {
        const uint32_t stb = sb + (uint32_t)stage * STAGE;
        #pragma unroll
        for (int i = 0; i < 4; i++) {        // A: 1024 16B chunks
            int idx = t + i * 256;
            int r = idx >> 3, c = idx & 7;
            uint32_t off = swz(r, c);
            size_t go = (size_t)(m0 + r) * lda + k0 + c * 8;
            cp16(stb + off, Ah + go);
            if (NPASS == 3) cp16(stb + APART + off, Al + go);
        }
        #pragma unroll
        for (int i = 0; i < 4; i++) {        // B
            int idx = t + i * 256;
            int r = idx >> 3, c = idx & 7;
            uint32_t off = swz(r, c);
            size_t go = (size_t)(n0 + r) * ldb + k0 + c * 8;
            cp16(stb + BOFF + off, Bh + go);
            if (NPASS == 3) cp16(stb + BOFF + APART + off, Bl + go);
        }
        cp_commit();
    };

    // per-lane ldmatrix pieces
    const int a_row = lane & 15;
    const int a_kh  = lane >> 4;
    const int b_row = (lane >> 4) * 8 + (lane & 7);
    const int b_kh  = (lane >> 3) & 1;

    #pragma unroll
    for (int s = 0; s < NSTAGE - 1; s++) {
        if (s < nch) load_chunk(s, s << 6); else cp_commit();
    }

    for (int i = 0; i < nch; i++) {
        cp_wait<NSTAGE - 2>();
        __syncthreads();
        const int j = i + NSTAGE - 1;
        if (j < nch) load_chunk(j % NSTAGE, j << 6); else cp_commit();

        const uint32_t stb = sb + (uint32_t)(i % NSTAGE) * STAGE;
        #pragma unroll
        for (int ks = 0; ks < 4; ks++) {
            uint32_t fa[4][4], fb[2][4];
            #pragma unroll
            for (int mt = 0; mt < 4; mt++) {
                int r = warp_m + mt * 16 + a_row;
                ldsm4(fa[mt], stb + swz(r, ks * 2 + a_kh));
            }
            #pragma unroll
            for (int pr = 0; pr < 2; pr++) {
                int r = warp_n + pr * 16 + b_row;
                ldsm4(fb[pr], stb + BOFF + swz(r, ks * 2 + b_kh));
            }
            #pragma unroll
            for (int mt = 0; mt < 4; mt++)
                #pragma unroll
                for (int nt = 0; nt < 4; nt++)
                    mma16816(acc[mt][nt], fa[mt], &fb[nt >> 1][(nt & 1) * 2]);

            if (NPASS == 3) {
                uint32_t fa2[4][4];
                #pragma unroll
                for (int mt = 0; mt < 4; mt++) {
                    int r = warp_m + mt * 16 + a_row;
                    ldsm4(fa2[mt], stb + APART + swz(r, ks * 2 + a_kh));
                }
                #pragma unroll
                for (int mt = 0; mt < 4; mt++)
                    #pragma unroll
                    for (int nt = 0; nt < 4; nt++)
                        mma16816(acc[mt][nt], fa2[mt], &fb[nt >> 1][(nt & 1) * 2]);
                #pragma unroll
                for (int pr = 0; pr < 2; pr++) {
                    int r = warp_n + pr * 16 + b_row;
                    ldsm4(fb[pr], stb + BOFF + APART + swz(r, ks * 2 + b_kh));
                }
                #pragma unroll
                for (int mt = 0; mt < 4; mt++)
                    #pragma unroll
                    for (int nt = 0; nt < 4; nt++)
                        mma16816(acc[mt][nt], fa[mt], &fb[nt >> 1][(nt & 1) * 2]);
            }
        }
    }

    // ---- epilogue ----
    #pragma unroll
    for (int mt = 0; mt < 4; mt++) {
        #pragma unroll
        for (int half = 0; half < 2; half++) {
            const int gr = m0 + warp_m + mt * 16 + (lane >> 2) + half * 8;
            #pragma unroll
            for (int nt = 0; nt < 4; nt++) {
                const int gc = n0 + warp_n + nt * 8 + 2 * (lane & 3);
                float v0 = acc[mt][nt][half * 2 + 0] * alpha;
                float v1 = acc[mt][nt][half * 2 + 1] * alpha;
                if (BIAS) { v0 += bias[gc]; v1 += bias[gc + 1]; }
                size_t o = (size_t)gr * ldc + gc;
                if (OUT == 0) {
                    *(float2*)(Cf + o) = make_float2(v0, v1);
                } else if (OUT == 2) {
                    bf16 h0 = __float2bfloat16(v0), h1 = __float2bfloat16(v1);
                    bf16 l0 = __float2bfloat16(v0 - __bfloat162float(h0));
                    bf16 l1 = __float2bfloat16(v1 - __bfloat162float(h1));
                    *(__nv_bfloat162*)(Ch + o) = __halves2bfloat162(h0, h1);
                    *(__nv_bfloat162*)(Cl + o) = __halves2bfloat162(l0, l1);
                } else {
                    *(__nv_bfloat162*)(Ch + o) = __floats2bfloat162_rn(v0, v1);
                }
            }
        }
    }
}

// ---------------- reductions ----------------
__device__ __forceinline__ float blockReduceSum(float v) {
    __shared__ float sh[32];
    int lane = threadIdx.x & 31, w = threadIdx.x >> 5;
    #pragma unroll
    for (int o = 16; o > 0; o >>= 1) v += __shfl_down_sync(0xffffffffu, v, o);
    __syncthreads();
    if (lane == 0) sh[w] = v;
    __syncthreads();
    float r = 0.f;
    if (threadIdx.x < (blockDim.x >> 5)) r = sh[threadIdx.x];
    if (w == 0) {
        #pragma unroll
        for (int o = 4; o > 0; o >>= 1) r += __shfl_down_sync(0xffffffffu, r, o);
    }
    if (threadIdx.x == 0) sh[0] = r;
    __syncthreads();
    return sh[0];
}
__device__ __forceinline__ float blockReduceMax(float v) {
    __shared__ float sh[32];
    int lane = threadIdx.x & 31, w = threadIdx.x >> 5;
    #pragma unroll
    for (int o = 16; o > 0; o >>= 1) v = fmaxf(v, __shfl_down_sync(0xffffffffu, v, o));
    __syncthreads();
    if (lane == 0) sh[w] = v;
    __syncthreads();
    float r = -INFINITY;
    if (threadIdx.x < (blockDim.x >> 5)) r = sh[threadIdx.x];
    if (w == 0) {
        #pragma unroll
        for (int o = 4; o > 0; o >>= 1) r = fmaxf(r, __shfl_down_sync(0xffffffffu, r, o));
    }
    if (threadIdx.x == 0) sh[0] = r;
    __syncthreads();
    return sh[0];
}

// ---------------- elementwise ----------------
__global__ void convert_split(const float* __restrict__ X, bf16* __restrict__ H,
                              bf16* __restrict__ L)
{
    size_t i = ((size_t)blockIdx.x * 256 + threadIdx.x) * 4;
    float4 v = *(const float4*)(X + i);
    float vv[4] = {v.x, v.y, v.z, v.w};
    #pragma unroll
    for (int k = 0; k < 4; k++) {
        bf16 h = __float2bfloat16(vv[k]);
        H[i + k] = h;
        L[i + k] = __float2bfloat16(vv[k] - __bfloat162float(h));
    }
}

__global__ void transpose_split(const float* __restrict__ W, bf16* __restrict__ Th,
                                bf16* __restrict__ Tl)
{
    __shared__ float tile[32][33];
    int x = blockIdx.x * 32 + threadIdx.x, y0 = blockIdx.y * 32;
    #pragma unroll
    for (int i = 0; i < 32; i += 8)
        tile[threadIdx.y + i][threadIdx.x] = W[(size_t)(y0 + threadIdx.y + i) * D_M + x];
    __syncthreads();
    int k = y0 + threadIdx.x;
    #pragma unroll
    for (int i = 0; i < 32; i += 8) {
        int n = blockIdx.x * 32 + threadIdx.y + i;
        float v = tile[threadIdx.x][threadIdx.y + i];
        bf16 h = __float2bfloat16(v);
        Th[(size_t)n * D_M + k] = h;
        Tl[(size_t)n * D_M + k] = __float2bfloat16(v - __bfloat162float(h));
    }
}

__global__ void ln_gelu_split(const float* __restrict__ X, const float* __restrict__ g,
                              const float* __restrict__ be, bf16* __restrict__ Yh,
                              bf16* __restrict__ Yl)
{
    const int row = blockIdx.x;
    const float* x = X + (size_t)row * D_M;
    float xv[4];
    #pragma unroll
    for (int i = 0; i < 4; i++) xv[i] = x[threadIdx.x + i * 256];
    float mu = blockReduceSum(xv[0] + xv[1] + xv[2] + xv[3]) * (1.f / D_M);
    float vs = 0.f;
    #pragma unroll
    for (int i = 0; i < 4; i++) { float d = xv[i] - mu; vs += d * d; }
    float rstd = rsqrtf(blockReduceSum(vs) * (1.f / D_M) + 1e-5f);
    #pragma unroll
    for (int i = 0; i < 4; i++) {
        int c = threadIdx.x + i * 256;
        float y = (xv[i] - mu) * rstd * g[c] + be[c];
        float o = y * 0.5f * (1.f + erff(y * 0.70710678118654752f));
        bf16 h = __float2bfloat16(o);
        Yh[(size_t)row * D_M + c] = h;
        Yl[(size_t)row * D_M + c] = __float2bfloat16(o - __bfloat162float(h));
    }
}

__global__ void row_stats_split(const bf16* __restrict__ H, const bf16* __restrict__ L,
                                float* __restrict__ sq, float* __restrict__ inv)
{
    const int row = blockIdx.x;
    float s = 0.f;
    for (int i = threadIdx.x; i < D_M; i += 256) {
        float v = __bfloat162float(H[(size_t)row * D_M + i]) +
                  __bfloat162float(L[(size_t)row * D_M + i]);
        s = fmaf(v, v, s);
    }
    float tot = blockReduceSum(s);
    if (threadIdx.x == 0) { sq[row] = tot; inv[row] = rsqrtf(tot); }
}

__global__ void softmax_stats(const bf16* __restrict__ Sc, float* __restrict__ m,
                              float* __restrict__ linv)
{
    const int r = blockIdx.x;
    const __nv_bfloat162* x = (const __nv_bfloat162*)(Sc + (size_t)r * N_C);
    float mx = -INFINITY;
    for (int i = threadIdx.x; i < N_C / 2; i += 256) {
        float2 v = __bfloat1622float2(x[i]);
        mx = fmaxf(mx, fmaxf(v.x, v.y));
    }
    mx = blockReduceMax(mx);
    float s = 0.f;
    for (int i = threadIdx.x; i < N_C / 2; i += 256) {
        float2 v = __bfloat1622float2(x[i]);
        s += __expf(v.x - mx) + __expf(v.y - mx);
    }
    float tot = blockReduceSum(s);
    if (threadIdx.x == 0) { m[r] = mx; linv[r] = 1.f / tot; }
}

__global__ __launch_bounds__(256)
void fuse(const float* __restrict__ S, const bf16* __restrict__ scores,
          const float* __restrict__ qsq, const float* __restrict__ qinv,
          const float* __restrict__ ksq, const float* __restrict__ kinv,
          const float* __restrict__ m, const float* __restrict__ linv,
          const float* __restrict__ temp,
          const float* __restrict__ fw1, const float* __restrict__ fb1,
          const float* __restrict__ fw2, const float* __restrict__ fb2,
          float* __restrict__ out)
{
    __shared__ float w1s[192], b1s[64], w2s[64], b2s, eT;
    const int t = threadIdx.x;
    if (t < 192) w1s[t] = fw1[t];
    if (t < 64) { b1s[t] = fb1[t]; w2s[t] = fw2[t]; }
    if (t == 0) { b2s = fb2[0]; eT = expf(temp[0]); }
    __syncthreads();

    size_t idx = (size_t)blockIdx.x * 256 + t;
    int b = (int)(idx >> 14), n = (int)(idx & (N_C - 1));

    float s = S[idx];
    float cosv = s * qinv[b] * kinv[n] * eT;
    float d2 = qsq[b] + ksq[n] - 2.f * s;
    float euc = 1.f / (1.f + sqrtf(fmaxf(d2, 0.f)));
    float ls = 0.f;
    #pragma unroll
    for (int h = 0; h < NH; h++) {
        int r = h * B_Q + b;
        ls += __expf(__bfloat162float(scores[(size_t)h * B_Q * N_C + idx]) - m[r]) * linv[r];
    }
    float learned = ls * (1.f / NH);

    float o = b2s;
    #pragma unroll
    for (int j = 0; j < 64; j++) {
        float hv = fmaf(cosv, w1s[j], fmaf(euc, w1s[64 + j],
                   fmaf(learned, w1s[128 + j], b1s[j])));
        o = fmaf(fmaxf(hv, 0.f), w2s[j], o);
    }
    out[idx] = 1.f / (1.f + __expf(-o));
}

// ---------------- launch ----------------
#define SMEM3 (3 * 65536)
#define SMEM1 (4 * 32768)

extern "C" void kernel_launch(void* const* d_in, const int* in_sizes, int n_in,
                              void* d_out, int out_size)
{
    (void)in_sizes; (void)n_in; (void)out_size;
    const float* qf   = (const float*)d_in[0];
    const float* cf   = (const float*)d_in[1];
    const float* temp = (const float*)d_in[2];
    const float* q_w1 = (const float*)d_in[3];
    const float* q_b1 = (const float*)d_in[4];
    const float* q_g  = (const float*)d_in[5];
    const float* q_be = (const float*)d_in[6];
    const float* q_w2 = (const float*)d_in[7];
    const float* q_b2 = (const float*)d_in[8];
    const float* k_w1 = (const float*)d_in[9];
    const float* k_b1 = (const float*)d_in[10];
    const float* k_g  = (const float*)d_in[11];
    const float* k_be = (const float*)d_in[12];
    const float* k_w2 = (const float*)d_in[13];
    const float* k_b2 = (const float*)d_in[14];
    const float* wq   = (const float*)d_in[15];
    const float* bq   = (const float*)d_in[16];
    const float* wk   = (const float*)d_in[17];
    const float* bk   = (const float*)d_in[18];
    const float* fw1  = (const float*)d_in[19];
    const float* fb1  = (const float*)d_in[20];
    const float* fw2  = (const float*)d_in[21];
    const float* fb2  = (const float*)d_in[22];
    float* out = (float*)d_out;

    bf16 *wth, *wtl, *cfh, *cfl, *qfh, *qfl, *Hh, *Hl;
    bf16 *kph, *kpl, *qph, *qpl, *kh, *qh, *sc;
    float *T, *S, *qsq, *qinv, *ksq, *kinv, *mm, *linv;
    cudaGetSymbolAddress((void**)&wth, g_wth);
    cudaGetSymbolAddress((void**)&wtl, g_wtl);
    cudaGetSymbolAddress((void**)&cfh, g_cfh);
    cudaGetSymbolAddress((void**)&cfl, g_cfl);
    cudaGetSymbolAddress((void**)&qfh, g_qfh);
    cudaGetSymbolAddress((void**)&qfl, g_qfl);
    cudaGetSymbolAddress((void**)&T,   g_T);
    cudaGetSymbolAddress((void**)&Hh,  g_Hh);
    cudaGetSymbolAddress((void**)&Hl,  g_Hl);
    cudaGetSymbolAddress((void**)&kph, g_kph);
    cudaGetSymbolAddress((void**)&kpl, g_kpl);
    cudaGetSymbolAddress((void**)&qph, g_qph);
    cudaGetSymbolAddress((void**)&qpl, g_qpl);
    cudaGetSymbolAddress((void**)&kh,  g_kh);
    cudaGetSymbolAddress((void**)&qh,  g_qh);
    cudaGetSymbolAddress((void**)&S,   g_S);
    cudaGetSymbolAddress((void**)&sc,  g_sc);
    cudaGetSymbolAddress((void**)&qsq, g_qsq);
    cudaGetSymbolAddress((void**)&qinv, g_qinv);
    cudaGetSymbolAddress((void**)&ksq, g_ksq);
    cudaGetSymbolAddress((void**)&kinv, g_kinv);
    cudaGetSymbolAddress((void**)&mm,  g_m);
    cudaGetSymbolAddress((void**)&linv, g_linv);

    cudaFuncSetAttribute(gemm_mma<3, 0, true,  3>, cudaFuncAttributeMaxDynamicSharedMemorySize, SMEM3);
    cudaFuncSetAttribute(gemm_mma<3, 2, true,  3>, cudaFuncAttributeMaxDynamicSharedMemorySize, SMEM3);
    cudaFuncSetAttribute(gemm_mma<3, 0, false, 3>, cudaFuncAttributeMaxDynamicSharedMemorySize, SMEM3);
    cudaFuncSetAttribute(gemm_mma<1, 3, true,  4>, cudaFuncAttributeMaxDynamicSharedMemorySize, SMEM1);
    cudaFuncSetAttribute(gemm_mma<1, 3, false, 4>, cudaFuncAttributeMaxDynamicSharedMemorySize, SMEM1);

    const size_t DD = (size_t)D_M * D_M;
    dim3 tgrid(D_M / 32, D_M / 32), tblk(32, 8);
    transpose_split<<<tgrid, tblk>>>(k_w1, wth + 0 * DD, wtl + 0 * DD);
    transpose_split<<<tgrid, tblk>>>(k_w2, wth + 1 * DD, wtl + 1 * DD);
    transpose_split<<<tgrid, tblk>>>(wk,   wth + 2 * DD, wtl + 2 * DD);
    transpose_split<<<tgrid, tblk>>>(q_w1, wth + 3 * DD, wtl + 3 * DD);
    transpose_split<<<tgrid, tblk>>>(q_w2, wth + 4 * DD, wtl + 4 * DD);
    transpose_split<<<tgrid, tblk>>>(wq,   wth + 5 * DD, wtl + 5 * DD);
    convert_split<<<(unsigned)((size_t)N_C * D_M / 1024), 256>>>(cf, cfh, cfl);
    convert_split<<<(unsigned)((size_t)B_Q * D_M / 1024), 256>>>(qf, qfh, qfl);

    const dim3 gK(D_M / 128, N_C / 128);   // (8, 128)
    const dim3 gQ(D_M / 128, B_Q / 128);   // (8, 8)

    // K path: Tk -> Hk -> kp(split) -> kh(bf16)
    gemm_mma<3, 0, true, 3><<<gK, 256, SMEM3>>>(cfh, cfl, wth + 0 * DD, wtl + 0 * DD,
        k_b1, T, 0, 0, D_M, D_M, D_M, D_M, 1.f, 0, 0, 0);
    ln_gelu_split<<<N_C, 256>>>(T, k_g, k_be, Hh, Hl);
    gemm_mma<3, 2, true, 3><<<gK, 256, SMEM3>>>(Hh, Hl, wth + 1 * DD, wtl + 1 * DD,
        k_b2, 0, kph, kpl, D_M, D_M, D_M, D_M, 1.f, 0, 0, 0);
    row_stats_split<<<N_C, 256>>>(kph, kpl, ksq, kinv);
    gemm_mma<1, 3, true, 4><<<gK, 256, SMEM1>>>(kph, 0, wth + 2 * DD, 0,
        bk, 0, kh, 0, D_M, D_M, D_M, D_M, 1.f, 0, 0, 0);

    // Q path
    gemm_mma<3, 0, true, 3><<<gQ, 256, SMEM3>>>(qfh, qfl, wth + 3 * DD, wtl + 3 * DD,
        q_b1, T, 0, 0, D_M, D_M, D_M, D_M, 1.f, 0, 0, 0);
    ln_gelu_split<<<B_Q, 256>>>(T, q_g, q_be, Hh, Hl);
    gemm_mma<3, 2, true, 3><<<gQ, 256, SMEM3>>>(Hh, Hl, wth + 4 * DD, wtl + 4 * DD,
        q_b2, 0, qph, qpl, D_M, D_M, D_M, D_M, 1.f, 0, 0, 0);
    row_stats_split<<<B_Q, 256>>>(qph, qpl, qsq, qinv);
    gemm_mma<1, 3, true, 4><<<gQ, 256, SMEM1>>>(qph, 0, wth + 5 * DD, 0,
        bq, 0, qh, 0, D_M, D_M, D_M, D_M, 1.f, 0, 0, 0);

    // S = qp @ kp^T (f32, split inputs)
    gemm_mma<3, 0, false, 3><<<dim3(N_C / 128, B_Q / 128), 256, SMEM3>>>(
        qph, qpl, kph, kpl, 0, S, 0, 0, D_M, D_M, D_M, N_C, 1.f, 0, 0, 0);

    // per-head scores (bf16), z = head
    gemm_mma<1, 3, false, 4><<<dim3(N_C / 128, B_Q / 128, NH), 256, SMEM1>>>(
        qh, 0, kh, 0, 0, 0, sc, 0, HDIM, D_M, D_M, N_C,
        0.08838834764831845f, HDIM, HDIM, (long long)B_Q * N_C);

    softmax_stats<<<NH * B_Q, 256>>>(sc, mm, linv);
    fuse<<<(unsigned)((size_t)B_Q * N_C / 256), 256>>>(
        S, sc, qsq, qinv, ksq, kinv, mm, linv, temp, fw1, fb1, fw2, fb2, out);
}